// round 8
// baseline (speedup 1.0000x reference)
#include <cuda_runtime.h>
#include <cuda_bf16.h>
#include <cuda_fp16.h>

// GCNLayer SpMM: out[i,:] = sum_{e: rows[e]==i} vals[e] * embeds[cols[e],:]
// N=10000 nodes, E=640000 edges, D=128 features.
//
// Round-8: the SpMM gather pass sits at the fp32 L2-traffic floor
// (640K x 512B = 328MB ~= 29us at the ~11TB/s LTS cap). Halve it: convert
// embeds to an fp16 __device__ cache once per call (~1us), gather 256B/edge,
// accumulate fp32. Expected output rel_err ~3e-4 (fp16 rounding / sqrt(3)),
// well under the 1e-3 gate. CSR build unchanged from round-7 (32-way
// replicated counters, transposed layout, warp-scan stagger).

static constexpr int MAX_N = 10000;
static constexpr int MAX_E = 640000;
static constexpr int D_FEAT = 128;
static constexpr int C_REP = 32;           // counter replication factor

__device__ int     g_count[MAX_N * C_REP];   // [row][replica]
__device__ int     g_cursor[MAX_N * C_REP];  // [row][replica] staggered cursors
__device__ int     g_total[MAX_N];           // per-row totals
__device__ int     g_start[MAX_N + 1];       // CSR row offsets
__device__ uint2   g_pairs[MAX_E];           // .x = col, .y = bits(val), row-sorted
__device__ __half  g_emb16[MAX_N * D_FEAT];  // fp16 embedding cache

// ---------------------------------------------------------------- convert
// embeds fp32 -> fp16 cache. One half2 (two feats) per thread.
__global__ void convert_kernel(const float2* __restrict__ emb, int n2) {
    int i = blockIdx.x * blockDim.x + threadIdx.x;
    if (i < n2) {
        float2 f = emb[i];
        ((__half2*)g_emb16)[i] = __floats2half2_rn(f.x, f.y);
    }
}

// ---------------------------------------------------------------- hist
// No-return atomicAdd -> RED. replica = e&31: each lane of a warp hits a
// different word of row r's 128B counter group -> no intra-warp conflicts.
__global__ void hist_kernel(const int* __restrict__ rows, int E) {
    int e = blockIdx.x * blockDim.x + threadIdx.x;
    if (e < E) {
        int r = rows[e];
        atomicAdd(&g_count[r * C_REP + (e & (C_REP - 1))], 1);
    }
}

// ---------------------------------------------------------------- reduce
// Warp per row, coalesced 128B load, warp-sum -> g_total[r].
__global__ void reduce_kernel(int n) {
    int warp = (blockIdx.x * blockDim.x + threadIdx.x) >> 5;
    int lane = threadIdx.x & 31;
    if (warp >= n) return;
    int c = g_count[warp * C_REP + lane];
    int t = __reduce_add_sync(0xffffffffu, c);
    if (lane == 0) g_total[warp] = t;
}

// ---------------------------------------------------------------- scan
// Single block, smem-staged, coalesced, register-light.
static constexpr int SCAN_THREADS = 1024;
static constexpr int SCAN_ITEMS   = 10;     // 10240 >= N
static constexpr int SCAN_SPAN    = SCAN_THREADS * SCAN_ITEMS;

__global__ __launch_bounds__(SCAN_THREADS) void scan_kernel(int n) {
    __shared__ int s_val[SCAN_SPAN];
    __shared__ int s_part[SCAN_THREADS];
    int tid = threadIdx.x;

    for (int i = tid; i < SCAN_SPAN; i += SCAN_THREADS)
        s_val[i] = (i < n) ? g_total[i] : 0;
    __syncthreads();

    int base = tid * SCAN_ITEMS;
    int loc[SCAN_ITEMS];
    int sum = 0;
    #pragma unroll
    for (int i = 0; i < SCAN_ITEMS; i++) { loc[i] = sum; sum += s_val[base + i]; }
    s_part[tid] = sum;
    __syncthreads();

    for (int off = 1; off < SCAN_THREADS; off <<= 1) {
        int t = (tid >= off) ? s_part[tid - off] : 0;
        __syncthreads();
        s_part[tid] += t;
        __syncthreads();
    }

    int prefix = (tid > 0) ? s_part[tid - 1] : 0;
    #pragma unroll
    for (int i = 0; i < SCAN_ITEMS; i++) s_val[base + i] = prefix + loc[i];
    __syncthreads();

    for (int i = tid; i < n; i += SCAN_THREADS) g_start[i] = s_val[i];
    if (tid == SCAN_THREADS - 1) g_start[n] = s_part[SCAN_THREADS - 1];
}

// ---------------------------------------------------------------- stagger
// Warp per row: shfl exclusive scan over the 32 replica counts.
__global__ void stagger_kernel(int n) {
    int warp = (blockIdx.x * blockDim.x + threadIdx.x) >> 5;
    int lane = threadIdx.x & 31;
    if (warp >= n) return;

    int cnt = g_count[warp * C_REP + lane];
    int x = cnt;
    #pragma unroll
    for (int off = 1; off < 32; off <<= 1) {
        int t = __shfl_up_sync(0xffffffffu, x, off);
        if (lane >= off) x += t;
    }
    int excl = x - cnt;                       // exclusive prefix
    g_cursor[warp * C_REP + lane] = g_start[warp] + excl;
}

// ---------------------------------------------------------------- scatter
// Returning atomic; ~2-deep contention over 320K cursor addresses.
__global__ void scatter_kernel(const int*   __restrict__ rows,
                               const int*   __restrict__ cols,
                               const float* __restrict__ vals,
                               int E) {
    int e = blockIdx.x * blockDim.x + threadIdx.x;
    if (e >= E) return;
    int r = rows[e];
    int pos = atomicAdd(&g_cursor[r * C_REP + (e & (C_REP - 1))], 1);
    g_pairs[pos] = make_uint2((unsigned)cols[e], __float_as_uint(vals[e]));
}

// ---------------------------------------------------------------- spmm
// Warp per row. fp16 gather: lane owns 4 features (8B of fp16), accumulates
// fp32, one STG.128 at the end. Out row = 512B fp32, lane l -> feats 4l..4l+3.
static constexpr int D_VEC16 = D_FEAT / 4;   // 32 uint2 (8B) chunks per fp16 row

__global__ __launch_bounds__(256) void spmm_csr_kernel(
    float4* __restrict__ out,    // [N, 32] float4
    int n)
{
    int warp = (blockIdx.x * blockDim.x + threadIdx.x) >> 5;
    int lane = threadIdx.x & 31;
    if (warp >= n) return;

    int j   = g_start[warp];
    int end = g_start[warp + 1];

    const uint2* emb16 = (const uint2*)g_emb16;   // 8B = 4 halves per lane

    float4 acc = make_float4(0.f, 0.f, 0.f, 0.f);

    while (end - j >= 32) {
        uint2 p = g_pairs[j + lane];
        #pragma unroll 8
        for (int k = 0; k < 32; k++) {
            int   c = __shfl_sync(0xffffffffu, (int)p.x, k);
            float v = __uint_as_float(__shfl_sync(0xffffffffu, p.y, k));
            uint2 h = __ldg(emb16 + c * D_VEC16 + lane);
            float2 f0 = __half22float2(*(const __half2*)&h.x);
            float2 f1 = __half22float2(*(const __half2*)&h.y);
            acc.x += v * f0.x; acc.y += v * f0.y;
            acc.z += v * f1.x; acc.w += v * f1.y;
        }
        j += 32;
    }

    int m = end - j;
    if (m > 0) {
        uint2 p = (lane < m) ? g_pairs[j + lane] : make_uint2(0u, 0u);
        for (int k = 0; k < m; k++) {
            int   c = __shfl_sync(0xffffffffu, (int)p.x, k);
            float v = __uint_as_float(__shfl_sync(0xffffffffu, p.y, k));
            uint2 h = __ldg(emb16 + c * D_VEC16 + lane);
            float2 f0 = __half22float2(*(const __half2*)&h.x);
            float2 f1 = __half22float2(*(const __half2*)&h.y);
            acc.x += v * f0.x; acc.y += v * f0.y;
            acc.z += v * f1.x; acc.w += v * f1.y;
        }
    }

    out[warp * 32 + lane] = acc;   // rows with no edges write zeros
}

// ----------------------------------------------------------------- launch
extern "C" void kernel_launch(void* const* d_in, const int* in_sizes, int n_in,
                              void* d_out, int out_size) {
    const int*   adj_rows = (const int*)  d_in[0];
    const int*   adj_cols = (const int*)  d_in[1];
    const float* adj_vals = (const float*)d_in[2];
    const float* embeds   = (const float*)d_in[3];
    float*       out      = (float*)d_out;

    const int E = in_sizes[0];           // 640000
    const int N = out_size / 128;        // 10000

    // Zero the replicated histograms via a memset node (capture-legal).
    void* count_ptr = nullptr;
    cudaGetSymbolAddress(&count_ptr, g_count);
    cudaMemsetAsync(count_ptr, 0, (size_t)MAX_N * C_REP * sizeof(int), 0);

    int n2 = N * D_FEAT / 2;             // half2 elements
    convert_kernel<<<(n2 + 255) / 256, 256>>>((const float2*)embeds, n2);

    hist_kernel<<<(E + 255) / 256, 256>>>(adj_rows, E);

    long long warp_threads = (long long)N * 32;
    int warp_blocks = (int)((warp_threads + 255) / 256);
    reduce_kernel<<<warp_blocks, 256>>>(N);
    scan_kernel<<<1, SCAN_THREADS>>>(N);
    stagger_kernel<<<warp_blocks, 256>>>(N);
    scatter_kernel<<<(E + 255) / 256, 256>>>(adj_rows, adj_cols, adj_vals, E);

    spmm_csr_kernel<<<warp_blocks, 256>>>((float4*)out, N);
}

// round 9
// speedup vs baseline: 1.3852x; 1.3852x over previous
#include <cuda_runtime.h>
#include <cuda_bf16.h>

// GCNLayer SpMM: out[i,:] = sum_{e: rows[e]==i} vals[e] * embeds[cols[e],:]
// N=10000 nodes, E=640000 edges, D=128 features.
//
// Round-9: fp32 spmm restored (round-8's fp16 gather lost ~15us to
// quarter-rate F2F unpack — conversion pipe, not bytes, was binding).
// CSR build: SpMM only needs CONTIGUOUS per-row regions, not ordered ones,
// so the entire prefix-scan chain (reduce 1us + single-block scan 13.5us +
// stagger 5us) is replaced by one fused warp-per-row span kernel using a
// global bump allocator (per-block atomicAdd). Pipeline:
//   memset counts -> hist (32-way replicated REDs) -> span (fused
//   reduce+alloc+cursor) -> scatter (low-contention returning atomics) ->
//   warp-per-row fp32 CSR spmm (L2-read floor ~29us).

static constexpr int MAX_N = 10000;
static constexpr int MAX_E = 640000;
static constexpr int D_VEC = 32;           // 128 floats = 32 float4 per row
static constexpr int C_REP = 32;           // counter replication factor

__device__ int   g_count[MAX_N * C_REP];   // [row][replica]
__device__ int   g_cursor[MAX_N * C_REP];  // [row][replica] staggered cursors
__device__ int2  g_span[MAX_N];            // .x = start, .y = end (unordered CSR)
__device__ int   g_alloc;                  // bump allocator head
__device__ uint2 g_pairs[MAX_E];           // .x = col, .y = bits(val)

// ---------------------------------------------------------------- hist
// No-return atomicAdd -> RED. replica = e&31: each lane of a warp hits a
// different word of row r's 128B counter group -> no intra-warp conflicts.
__global__ void hist_kernel(const int* __restrict__ rows, int E) {
    int e = blockIdx.x * blockDim.x + threadIdx.x;
    if (e < E) {
        int r = rows[e];
        atomicAdd(&g_count[r * C_REP + (e & (C_REP - 1))], 1);
    }
}

// ---------------------------------------------------------------- span
// Warp per row, 8 rows per block. Fuses: replica-count reduce, row-region
// allocation (block-aggregated bump atomic), span + staggered cursor write.
// No prefix scan anywhere; rows land in g_pairs in arbitrary but contiguous,
// disjoint regions.
__global__ __launch_bounds__(256) void span_kernel(int n) {
    __shared__ int s_total[8];
    __shared__ int s_base[8];
    int wid  = threadIdx.x >> 5;
    int lane = threadIdx.x & 31;
    int r    = blockIdx.x * 8 + wid;

    int cnt = (r < n) ? g_count[r * C_REP + lane] : 0;

    // warp inclusive scan over 32 replica counts
    int x = cnt;
    #pragma unroll
    for (int off = 1; off < 32; off <<= 1) {
        int t = __shfl_up_sync(0xffffffffu, x, off);
        if (lane >= off) x += t;
    }
    int total = __shfl_sync(0xffffffffu, x, 31);
    if (lane == 31) s_total[wid] = x;
    __syncthreads();

    // warp 0: scan the 8 per-row totals, one bump atomic per block
    if (wid == 0 && lane < 8) {
        int t = s_total[lane];
        int y = t;
        #pragma unroll
        for (int off = 1; off < 8; off <<= 1) {
            int u = __shfl_up_sync(0x000000ffu, y, off);
            if (lane >= off) y += u;
        }
        int blocktot = __shfl_sync(0x000000ffu, y, 7);
        int base = 0;
        if (lane == 7) base = atomicAdd(&g_alloc, blocktot);
        base = __shfl_sync(0x000000ffu, base, 7);
        s_base[lane] = base + (y - t);      // exclusive prefix within block
    }
    __syncthreads();

    if (r < n) {
        int base = s_base[wid];
        g_cursor[r * C_REP + lane] = base + (x - cnt);   // exclusive prefix
        if (lane == 0) g_span[r] = make_int2(base, base + total);
    }
}

// ---------------------------------------------------------------- scatter
// Returning atomic; ~2-deep contention over 320K cursor addresses.
__global__ void scatter_kernel(const int*   __restrict__ rows,
                               const int*   __restrict__ cols,
                               const float* __restrict__ vals,
                               int E) {
    int e = blockIdx.x * blockDim.x + threadIdx.x;
    if (e >= E) return;
    int r = rows[e];
    int pos = atomicAdd(&g_cursor[r * C_REP + (e & (C_REP - 1))], 1);
    g_pairs[pos] = make_uint2((unsigned)cols[e], __float_as_uint(vals[e]));
}

// ---------------------------------------------------------------- spmm
// Warp per row: lane owns one float4 (16B) chunk of the 512B output row.
__global__ __launch_bounds__(256) void spmm_csr_kernel(
    const float4* __restrict__ emb,    // [N, 32] float4
    float4*       __restrict__ out,    // [N, 32] float4
    int n)
{
    int warp = (blockIdx.x * blockDim.x + threadIdx.x) >> 5;
    int lane = threadIdx.x & 31;
    if (warp >= n) return;

    int2 se = g_span[warp];
    int j   = se.x;
    int end = se.y;

    float4 acc = make_float4(0.f, 0.f, 0.f, 0.f);

    while (end - j >= 32) {
        uint2 p = g_pairs[j + lane];
        #pragma unroll 8
        for (int k = 0; k < 32; k++) {
            int   c = __shfl_sync(0xffffffffu, (int)p.x, k);
            float v = __uint_as_float(__shfl_sync(0xffffffffu, p.y, k));
            float4 x = __ldg(emb + c * D_VEC + lane);
            acc.x += v * x.x; acc.y += v * x.y;
            acc.z += v * x.z; acc.w += v * x.w;
        }
        j += 32;
    }

    int m = end - j;
    if (m > 0) {
        uint2 p = (lane < m) ? g_pairs[j + lane] : make_uint2(0u, 0u);
        for (int k = 0; k < m; k++) {
            int   c = __shfl_sync(0xffffffffu, (int)p.x, k);
            float v = __uint_as_float(__shfl_sync(0xffffffffu, p.y, k));
            float4 x = __ldg(emb + c * D_VEC + lane);
            acc.x += v * x.x; acc.y += v * x.y;
            acc.z += v * x.z; acc.w += v * x.w;
        }
    }

    out[warp * D_VEC + lane] = acc;   // rows with no edges write zeros
}

// ----------------------------------------------------------------- launch
extern "C" void kernel_launch(void* const* d_in, const int* in_sizes, int n_in,
                              void* d_out, int out_size) {
    const int*   adj_rows = (const int*)  d_in[0];
    const int*   adj_cols = (const int*)  d_in[1];
    const float* adj_vals = (const float*)d_in[2];
    const float* embeds   = (const float*)d_in[3];
    float*       out      = (float*)d_out;

    const int E = in_sizes[0];           // 640000
    const int N = out_size / 128;        // 10000

    // Zero histograms + bump allocator via memset nodes (capture-legal).
    void* p = nullptr;
    cudaGetSymbolAddress(&p, g_count);
    cudaMemsetAsync(p, 0, (size_t)MAX_N * C_REP * sizeof(int), 0);
    cudaGetSymbolAddress(&p, g_alloc);
    cudaMemsetAsync(p, 0, sizeof(int), 0);

    hist_kernel<<<(E + 255) / 256, 256>>>(adj_rows, E);

    span_kernel<<<(N + 7) / 8, 256>>>(N);

    scatter_kernel<<<(E + 255) / 256, 256>>>(adj_rows, adj_cols, adj_vals, E);

    long long warp_threads = (long long)N * 32;
    int warp_blocks = (int)((warp_threads + 255) / 256);
    spmm_csr_kernel<<<warp_blocks, 256>>>((const float4*)embeds, (float4*)out, N);
}

// round 10
// speedup vs baseline: 1.4062x; 1.0152x over previous
#include <cuda_runtime.h>
#include <cuda_bf16.h>

// GCNLayer SpMM: out[i,:] = sum_{e: rows[e]==i} vals[e] * embeds[cols[e],:]
// N=10000 nodes, E=640000 edges, D=128 features.
//
// Round-10: round-9's warp-per-row spmm was latency-bound (L2=46%, issue=39%,
// occ=57% -- nothing saturated; one warp serializes 64 gather iterations with
// MLP capped by 38 regs). Switch to BLOCK-per-row: 8 warps split the row's
// edges 8-way, pairs are read via lane-uniform broadcast LDG (no shfl
// dependency), partials combined through a 4KB smem tree + single STG.128.
// ~8x more outstanding gathers chip-wide -> drive L2 toward its cap.
// CSR build unchanged: 32-way replicated hist REDs, fused span/bump-alloc
// kernel (no prefix scan), low-contention scatter.

static constexpr int MAX_N = 10000;
static constexpr int MAX_E = 640000;
static constexpr int D_VEC = 32;           // 128 floats = 32 float4 per row
static constexpr int C_REP = 32;           // counter replication factor

__device__ int   g_count[MAX_N * C_REP];   // [row][replica]
__device__ int   g_cursor[MAX_N * C_REP];  // [row][replica] staggered cursors
__device__ int2  g_span[MAX_N];            // .x = start, .y = end (unordered CSR)
__device__ int   g_alloc;                  // bump allocator head
__device__ uint2 g_pairs[MAX_E];           // .x = col, .y = bits(val)

// ---------------------------------------------------------------- hist
// No-return atomicAdd -> RED. replica = e&31: each lane of a warp hits a
// different word of row r's 128B counter group -> no intra-warp conflicts.
__global__ void hist_kernel(const int* __restrict__ rows, int E) {
    int e = blockIdx.x * blockDim.x + threadIdx.x;
    if (e < E) {
        int r = rows[e];
        atomicAdd(&g_count[r * C_REP + (e & (C_REP - 1))], 1);
    }
}

// ---------------------------------------------------------------- span
// Warp per row, 8 rows per block. Fuses: replica-count reduce, row-region
// allocation (block-aggregated bump atomic), span + staggered cursor write.
__global__ __launch_bounds__(256) void span_kernel(int n) {
    __shared__ int s_total[8];
    __shared__ int s_base[8];
    int wid  = threadIdx.x >> 5;
    int lane = threadIdx.x & 31;
    int r    = blockIdx.x * 8 + wid;

    int cnt = (r < n) ? g_count[r * C_REP + lane] : 0;

    int x = cnt;
    #pragma unroll
    for (int off = 1; off < 32; off <<= 1) {
        int t = __shfl_up_sync(0xffffffffu, x, off);
        if (lane >= off) x += t;
    }
    int total = __shfl_sync(0xffffffffu, x, 31);
    if (lane == 31) s_total[wid] = x;
    __syncthreads();

    if (wid == 0 && lane < 8) {
        int t = s_total[lane];
        int y = t;
        #pragma unroll
        for (int off = 1; off < 8; off <<= 1) {
            int u = __shfl_up_sync(0x000000ffu, y, off);
            if (lane >= off) y += u;
        }
        int blocktot = __shfl_sync(0x000000ffu, y, 7);
        int base = 0;
        if (lane == 7) base = atomicAdd(&g_alloc, blocktot);
        base = __shfl_sync(0x000000ffu, base, 7);
        s_base[lane] = base + (y - t);
    }
    __syncthreads();

    if (r < n) {
        int base = s_base[wid];
        g_cursor[r * C_REP + lane] = base + (x - cnt);
        if (lane == 0) g_span[r] = make_int2(base, base + total);
    }
}

// ---------------------------------------------------------------- scatter
// Returning atomic; ~2-deep contention over 320K cursor addresses.
__global__ void scatter_kernel(const int*   __restrict__ rows,
                               const int*   __restrict__ cols,
                               const float* __restrict__ vals,
                               int E) {
    int e = blockIdx.x * blockDim.x + threadIdx.x;
    if (e >= E) return;
    int r = rows[e];
    int pos = atomicAdd(&g_cursor[r * C_REP + (e & (C_REP - 1))], 1);
    g_pairs[pos] = make_uint2((unsigned)cols[e], __float_as_uint(vals[e]));
}

// ---------------------------------------------------------------- spmm
// BLOCK per row: 8 warps split the edge list 8-way; lane owns one float4
// chunk of the 512B output row. Pairs read as lane-uniform broadcast LDGs
// (single sector, no shfl chain). Partials combined via smem, one STG.128.
__global__ __launch_bounds__(256) void spmm_block_kernel(
    const float4* __restrict__ emb,    // [N, 32] float4
    float4*       __restrict__ out)    // [N, 32] float4
{
    __shared__ float4 s_acc[8][32];

    int row  = blockIdx.x;
    int wid  = threadIdx.x >> 5;
    int lane = threadIdx.x & 31;

    int2 se  = g_span[row];

    float4 acc = make_float4(0.f, 0.f, 0.f, 0.f);

    // Warp wid takes edges se.x+wid, +8, +16, ... Independent iterations:
    // ptxas can keep several gather LDG.128s in flight per warp.
    #pragma unroll 4
    for (int j = se.x + wid; j < se.y; j += 8) {
        uint2 p = __ldg(&g_pairs[j]);          // uniform across warp
        float v = __uint_as_float(p.y);
        float4 x = __ldg(emb + (int)p.x * D_VEC + lane);
        acc.x += v * x.x; acc.y += v * x.y;
        acc.z += v * x.z; acc.w += v * x.w;
    }

    s_acc[wid][lane] = acc;
    __syncthreads();

    // Warp 0 folds the 8 partials per chunk and writes the row.
    if (wid == 0) {
        float4 r = s_acc[0][lane];
        #pragma unroll
        for (int w = 1; w < 8; w++) {
            float4 t = s_acc[w][lane];
            r.x += t.x; r.y += t.y; r.z += t.z; r.w += t.w;
        }
        out[row * D_VEC + lane] = r;           // degree-0 rows write zeros
    }
}

// ----------------------------------------------------------------- launch
extern "C" void kernel_launch(void* const* d_in, const int* in_sizes, int n_in,
                              void* d_out, int out_size) {
    const int*   adj_rows = (const int*)  d_in[0];
    const int*   adj_cols = (const int*)  d_in[1];
    const float* adj_vals = (const float*)d_in[2];
    const float* embeds   = (const float*)d_in[3];
    float*       out      = (float*)d_out;

    const int E = in_sizes[0];           // 640000
    const int N = out_size / 128;        // 10000

    // Zero histograms + bump allocator via memset nodes (capture-legal).
    void* p = nullptr;
    cudaGetSymbolAddress(&p, g_count);
    cudaMemsetAsync(p, 0, (size_t)MAX_N * C_REP * sizeof(int), 0);
    cudaGetSymbolAddress(&p, g_alloc);
    cudaMemsetAsync(p, 0, sizeof(int), 0);

    hist_kernel<<<(E + 255) / 256, 256>>>(adj_rows, E);
    span_kernel<<<(N + 7) / 8, 256>>>(N);
    scatter_kernel<<<(E + 255) / 256, 256>>>(adj_rows, adj_cols, adj_vals, E);

    spmm_block_kernel<<<N, 256>>>((const float4*)embeds, (float4*)out);
}